// round 1
// baseline (speedup 1.0000x reference)
#include <cuda_runtime.h>

#define BM 128
#define BN 128
#define BK 16
#define TM 8
#define TN 8
#define NTHREADS 256

namespace {
constexpr int B_ = 32, N_ = 25, D_ = 512, H_ = 512, C_ = 1000;
constexpr int NP = N_ * N_;           // 625 pairs per batch
constexpr int M_PAIRS = B_ * NP;      // 20000
constexpr int M_ROWS = B_ * N_;       // 800
}

// Scratch (allocation-free: static device globals)
__device__ float g_U[M_ROWS * H_];                 // x @ W1_top + b1
__device__ float g_V[M_ROWS * H_];                 // x @ W1_bot
__device__ float g_H2[(size_t)M_PAIRS * H_];       // layer-2 activations
__device__ float g_H3[(size_t)M_PAIRS * H_];       // layer-3 activations
__device__ float g_AGG[B_ * H_];
__device__ float g_Z1[B_ * H_];
__device__ float g_Z2[B_ * H_];

// Tiled SGEMM, N=K=512 fixed. AMODE: 0 = plain A[M,512]; 1 = A row m is
// relu(U[b*25+i] + V[b*25+j]) generated on the fly (m = b*625 + i*25 + j).
template<int AMODE, bool RELU>
__global__ __launch_bounds__(NTHREADS, 2)
void gemm512(const float* __restrict__ A,
             const float* __restrict__ Bw,
             const float* __restrict__ bias,
             float* __restrict__ Cout, int M)
{
    __shared__ float As[BK][BM + 4];
    __shared__ float Bs[BK][BN];

    const int tid  = threadIdx.x;
    const int row0 = blockIdx.y * BM;
    const int col0 = blockIdx.x * BN;
    const int tx   = tid & 15;        // 16 cols of threads
    const int ty   = tid >> 4;        // 16 rows of threads

    // A tile load mapping: thread loads 2 float4s (rows a_r and a_r+64, 4 k's)
    const int a_r = tid >> 2;
    const int a_k = (tid & 3) << 2;

    const float* aptr0[2];
    const float* aptr1[2];
    bool avalid[2];
    #pragma unroll
    for (int ld = 0; ld < 2; ld++) {
        int m = row0 + a_r + ld * 64;
        avalid[ld] = (m < M);
        int mm = avalid[ld] ? m : 0;
        if (AMODE == 1) {
            int b = mm / NP;
            int r = mm - b * NP;
            int i = r / N_;
            int j = r - i * N_;
            aptr0[ld] = g_U + (size_t)(b * N_ + i) * 512;
            aptr1[ld] = g_V + (size_t)(b * N_ + j) * 512;
        } else {
            aptr0[ld] = A + (size_t)mm * 512;
            aptr1[ld] = nullptr;
        }
    }

    float acc[TM][TN] = {};

    for (int kt = 0; kt < 512; kt += BK) {
        // ---- load A tile (transposed into As[k][m]) ----
        #pragma unroll
        for (int ld = 0; ld < 2; ld++) {
            int ar = a_r + ld * 64;
            float4 av = make_float4(0.f, 0.f, 0.f, 0.f);
            if (avalid[ld]) {
                if (AMODE == 1) {
                    float4 u = *(const float4*)(aptr0[ld] + kt + a_k);
                    float4 v = *(const float4*)(aptr1[ld] + kt + a_k);
                    av.x = fmaxf(u.x + v.x, 0.f);
                    av.y = fmaxf(u.y + v.y, 0.f);
                    av.z = fmaxf(u.z + v.z, 0.f);
                    av.w = fmaxf(u.w + v.w, 0.f);
                } else {
                    av = *(const float4*)(aptr0[ld] + kt + a_k);
                }
            }
            As[a_k + 0][ar] = av.x;
            As[a_k + 1][ar] = av.y;
            As[a_k + 2][ar] = av.z;
            As[a_k + 3][ar] = av.w;
        }
        // ---- load B tile ----
        #pragma unroll
        for (int ld = 0; ld < 2; ld++) {
            int s  = tid + ld * NTHREADS;
            int br = s >> 5;
            int bc = (s & 31) << 2;
            *(float4*)&Bs[br][bc] =
                *(const float4*)(Bw + (size_t)(kt + br) * 512 + col0 + bc);
        }
        __syncthreads();

        #pragma unroll
        for (int k = 0; k < BK; k++) {
            float4 a0 = *(const float4*)&As[k][ty * TM];
            float4 a1 = *(const float4*)&As[k][ty * TM + 4];
            float4 b0 = *(const float4*)&Bs[k][tx * TN];
            float4 b1 = *(const float4*)&Bs[k][tx * TN + 4];
            float ra[8] = {a0.x, a0.y, a0.z, a0.w, a1.x, a1.y, a1.z, a1.w};
            float rb[8] = {b0.x, b0.y, b0.z, b0.w, b1.x, b1.y, b1.z, b1.w};
            #pragma unroll
            for (int i = 0; i < TM; i++)
                #pragma unroll
                for (int j = 0; j < TN; j++)
                    acc[i][j] = fmaf(ra[i], rb[j], acc[i][j]);
        }
        __syncthreads();
    }

    #pragma unroll
    for (int i = 0; i < TM; i++) {
        int m = row0 + ty * TM + i;
        if (m >= M) continue;
        #pragma unroll
        for (int j = 0; j < TN; j += 4) {
            int n = col0 + tx * TN + j;
            float4 o;
            o.x = acc[i][j + 0];
            o.y = acc[i][j + 1];
            o.z = acc[i][j + 2];
            o.w = acc[i][j + 3];
            if (bias) {
                o.x += bias[n + 0]; o.y += bias[n + 1];
                o.z += bias[n + 2]; o.w += bias[n + 3];
            }
            if (RELU) {
                o.x = fmaxf(o.x, 0.f); o.y = fmaxf(o.y, 0.f);
                o.z = fmaxf(o.z, 0.f); o.w = fmaxf(o.w, 0.f);
            }
            *(float4*)(Cout + (size_t)m * 512 + n) = o;
        }
    }
}

// agg[b,h] = sum_{i != j} h3[b,i,j,h]
__global__ void reduce_pairs_kernel(float* __restrict__ AGG)
{
    int idx = blockIdx.x * blockDim.x + threadIdx.x;
    if (idx >= B_ * H_) return;
    int b = idx >> 9;
    int h = idx & 511;
    const float* base = g_H3 + (size_t)b * NP * 512 + h;
    float s = 0.f;
    #pragma unroll 5
    for (int p = 0; p < NP; p++) s += base[(size_t)p * 512];
    #pragma unroll
    for (int i = 0; i < N_; i++) s -= base[(size_t)(i * N_ + i) * 512];
    AGG[idx] = s;
}

// Small fully-connected: one block per batch row, K=512
template<bool RELU>
__global__ void fc_kernel(const float* __restrict__ X, const float* __restrict__ W,
                          const float* __restrict__ bias, float* __restrict__ Y,
                          int Nout)
{
    __shared__ float xs[512];
    int b = blockIdx.x;
    for (int k = threadIdx.x; k < 512; k += blockDim.x) xs[k] = X[b * 512 + k];
    __syncthreads();
    for (int n = threadIdx.x; n < Nout; n += blockDim.x) {
        float s = bias[n];
        #pragma unroll 8
        for (int k = 0; k < 512; k++) s = fmaf(xs[k], W[k * Nout + n], s);
        if (RELU) s = fmaxf(s, 0.f);
        Y[b * Nout + n] = s;
    }
}

extern "C" void kernel_launch(void* const* d_in, const int* in_sizes, int n_in,
                              void* d_out, int out_size)
{
    const float* x    = (const float*)d_in[0];
    const float* g_w1 = (const float*)d_in[1];
    const float* g_b1 = (const float*)d_in[2];
    const float* g_w2 = (const float*)d_in[3];
    const float* g_b2 = (const float*)d_in[4];
    const float* g_w3 = (const float*)d_in[5];
    const float* g_b3 = (const float*)d_in[6];
    const float* f_w1 = (const float*)d_in[7];
    const float* f_b1 = (const float*)d_in[8];
    const float* f_w2 = (const float*)d_in[9];
    const float* f_b2 = (const float*)d_in[10];
    const float* f_w3 = (const float*)d_in[11];
    const float* f_b3 = (const float*)d_in[12];
    float* out = (float*)d_out;

    float *pU, *pV, *pH2, *pH3, *pAGG, *pZ1, *pZ2;
    cudaGetSymbolAddress((void**)&pU,   g_U);
    cudaGetSymbolAddress((void**)&pV,   g_V);
    cudaGetSymbolAddress((void**)&pH2,  g_H2);
    cudaGetSymbolAddress((void**)&pH3,  g_H3);
    cudaGetSymbolAddress((void**)&pAGG, g_AGG);
    cudaGetSymbolAddress((void**)&pZ1,  g_Z1);
    cudaGetSymbolAddress((void**)&pZ2,  g_Z2);

    // U = x @ W1[0:512] + b1 ;  V = x @ W1[512:1024]  (first layer factorized)
    dim3 gsmall(BN == 128 ? 4 : 512 / BN, (M_ROWS + BM - 1) / BM);
    gemm512<0, false><<<gsmall, NTHREADS>>>(x, g_w1, g_b1, pU, M_ROWS);
    gemm512<0, false><<<gsmall, NTHREADS>>>(x, g_w1 + 512 * 512, nullptr, pV, M_ROWS);

    // h2 = relu( relu(U_i + V_j) @ W2 + b2 )   -- h1 generated in the A loader
    dim3 gbig(4, (M_PAIRS + BM - 1) / BM);
    gemm512<1, true><<<gbig, NTHREADS>>>(nullptr, g_w2, g_b2, pH2, M_PAIRS);

    // h3 = relu( h2 @ W3 + b3 )
    gemm512<0, true><<<gbig, NTHREADS>>>(pH2, g_w3, g_b3, pH3, M_PAIRS);

    // agg over pairs with i != j
    reduce_pairs_kernel<<<(B_ * H_ + 255) / 256, 256>>>(pAGG);

    // f head
    fc_kernel<true ><<<B_, 512>>>(pAGG, f_w1, f_b1, pZ1, 512);
    fc_kernel<true ><<<B_, 512>>>(pZ1,  f_w2, f_b2, pZ2, 512);
    fc_kernel<false><<<B_, 512>>>(pZ2,  f_w3, f_b3, out, 1000);
}

// round 3
// speedup vs baseline: 2.1600x; 2.1600x over previous
#include <cuda_runtime.h>

typedef unsigned int u32;

namespace {
constexpr int B_ = 32, N_ = 25, H_ = 512, C_ = 1000;
constexpr int NP      = N_ * N_;   // 625
constexpr int M_PAIRS = B_ * NP;   // 20000
constexpr int M_ROWS  = B_ * N_;   // 800
constexpr int SLICES  = 5;

// smem layout (u32 units): per buffer: A frags 32 tiles * 132, B frags 64 tiles * 66
constexpr int ABUF      = 32 * 132;          // 4224 u32
constexpr int BBUF      = 64 * 66;           // 4224 u32
constexpr int BUFSTRIDE = ABUF + BBUF;       // 8448 u32
constexpr int SMEM_BYTES = 2 * BUFSTRIDE * 4; // 67584 B
}

// ---------------- scratch (allocation-free device globals) ----------------
__device__ float g_U [M_ROWS * H_];
__device__ float g_V [M_ROWS * H_];
__device__ float g_H2[(size_t)M_PAIRS * H_];
__device__ float g_H3[(size_t)M_PAIRS * H_];
__device__ float g_PART[SLICES * B_ * H_];
__device__ float g_AGG[B_ * H_];
__device__ float g_Z1 [B_ * H_];
__device__ float g_Z2 [B_ * H_];

// ---------------- helpers ----------------
__device__ __forceinline__ u32 tf32u(float x) {
    u32 r; asm("cvt.rna.tf32.f32 %0, %1;" : "=r"(r) : "f"(x));
    return r;
}
__device__ __forceinline__ void mma8(float* d, const u32* a, const u32* b) {
    asm volatile(
        "mma.sync.aligned.m16n8k8.row.col.f32.tf32.tf32.f32 "
        "{%0,%1,%2,%3}, {%4,%5,%6,%7}, {%8,%9}, {%0,%1,%2,%3};\n"
        : "+f"(d[0]), "+f"(d[1]), "+f"(d[2]), "+f"(d[3])
        : "r"(a[0]), "r"(a[1]), "r"(a[2]), "r"(a[3]), "r"(b[0]), "r"(b[1]));
}

// ======================================================================
// tf32 tensor-core GEMM: C[M,512] = A[M,512] @ W  (W row-major [512,512])
// tile 128m x 128n x 32k, double-buffered, fragments pre-scattered in smem.
// AMODE 1: A row m = relu(U[b,i] + V[b,j]) generated on the fly.
// ======================================================================
template<int AMODE, int RELU>
__global__ __launch_bounds__(256, 2)
void gemm_tc(const float* __restrict__ A, const float* __restrict__ Bw,
             const float* __restrict__ bias, float* __restrict__ C, int M)
{
    extern __shared__ u32 smem[];

    const int tid  = threadIdx.x;
    const int lane = tid & 31;
    const int wid  = tid >> 5;
    const int wm   = wid >> 1;       // 0..3
    const int wn   = wid & 1;        // 0..1
    const int m0   = blockIdx.y * 128;
    const int n0   = blockIdx.x * 128;

    // ---- producer mappings ----
    const int lr8 = tid >> 3;        // A: row within pass (0..31)
    const int kq  = tid & 7;         // A: k float4-group (k = kq*4)
    const int kb8 = tid >> 5;        // B: k row base (0..7), k = kb8 + 8q
    const int n4  = (tid & 31) * 4;  // B: n offset

    const float* pu[4];
    const float* pv[4];
    #pragma unroll
    for (int q = 0; q < 4; q++) {
        int m = m0 + lr8 + 32 * q;
        if (m >= M) m = 0;           // clamp; stores are masked
        if (AMODE == 1) {
            int b = m / NP; int r = m - b * NP;
            int i = r / N_; int j = r - i * N_;
            pu[q] = g_U + (size_t)(b * N_ + i) * 512;
            pv[q] = g_V + (size_t)(b * N_ + j) * 512;
        } else {
            pu[q] = A + (size_t)m * 512;
        }
    }

    float4 sau[4], sav[4], sb[4];

    auto ldg_stage = [&](int kt) {
        const int kb = kt * 32 + kq * 4;
        #pragma unroll
        for (int q = 0; q < 4; q++) {
            sau[q] = *(const float4*)(pu[q] + kb);
            if (AMODE == 1) sav[q] = *(const float4*)(pv[q] + kb);
        }
        const int kbB = kt * 32 + kb8;
        #pragma unroll
        for (int q = 0; q < 4; q++)
            sb[q] = *(const float4*)(Bw + (size_t)(kbB + 8 * q) * 512 + n0 + n4);
    };

    // A fragment scatter: tile (mt,ktile) holds lane-major a0..a3
    auto sts_a = [&](int buf) {
        u32* base = smem + buf * BUFSTRIDE;
        const int ktile = kq >> 1;
        const int slot0 = 2 * (kq & 1);       // k half selects slots {0,1} vs {2,3}
        #pragma unroll
        for (int q = 0; q < 4; q++) {
            const int ml = lr8 + 32 * q;
            const int mt = ml >> 4;
            const int r  = ml & 7;
            const int hm = (ml >> 3) & 1;     // m half: a0/a2 vs a1/a3
            u32* dst = base + (mt * 4 + ktile) * 132 + r * 16 + slot0 + hm;
            float v0, v1, v2, v3;
            if (AMODE == 1) {
                v0 = fmaxf(sau[q].x + sav[q].x, 0.f);
                v1 = fmaxf(sau[q].y + sav[q].y, 0.f);
                v2 = fmaxf(sau[q].z + sav[q].z, 0.f);
                v3 = fmaxf(sau[q].w + sav[q].w, 0.f);
            } else {
                v0 = sau[q].x; v1 = sau[q].y; v2 = sau[q].z; v3 = sau[q].w;
            }
            dst[0]  = tf32u(v0);
            dst[4]  = tf32u(v1);
            dst[8]  = tf32u(v2);
            dst[12] = tf32u(v3);
        }
    };

    auto sts_b = [&](int buf) {
        u32* base = smem + buf * BUFSTRIDE + ABUF;
        const int c    = kb8 & 3;
        const int slot = kb8 >> 2;
        #pragma unroll
        for (int q = 0; q < 4; q++) {         // ktile == q
            float vv[4] = { sb[q].x, sb[q].y, sb[q].z, sb[q].w };
            #pragma unroll
            for (int j = 0; j < 4; j++) {
                const int nn = n4 + j;
                base[(q * 16 + (nn >> 3)) * 66 + ((nn & 7) * 4 + c) * 2 + slot]
                    = tf32u(vv[j]);
            }
        }
    };

    float acc[2][8][4] = {};

    // prologue
    ldg_stage(0);
    sts_a(0);
    sts_b(0);
    __syncthreads();

    for (int kt = 0; kt < 16; kt++) {
        const int buf  = kt & 1;
        const bool more = (kt < 15);
        if (more) ldg_stage(kt + 1);
        if (more) sts_a(buf ^ 1);            // A staging dies before MMA section

        const u32* ab = smem + buf * BUFSTRIDE;
        const u32* bb = ab + ABUF;
        #pragma unroll
        for (int ks = 0; ks < 4; ks++) {
            uint4 af0 = *(const uint4*)(ab + ((wm * 2 + 0) * 4 + ks) * 132 + lane * 4);
            uint4 af1 = *(const uint4*)(ab + ((wm * 2 + 1) * 4 + ks) * 132 + lane * 4);
            #pragma unroll
            for (int j = 0; j < 8; j++) {
                uint2 bf = *(const uint2*)(bb + (ks * 16 + wn * 8 + j) * 66 + lane * 2);
                mma8(acc[0][j], (const u32*)&af0, (const u32*)&bf);
                mma8(acc[1][j], (const u32*)&af1, (const u32*)&bf);
            }
        }
        if (more) sts_b(buf ^ 1);
        __syncthreads();
    }

    // ---- epilogue: bias + relu, direct fp32 stores ----
    const int cbase = n0 + wn * 64 + (lane & 3) * 2;
    #pragma unroll
    for (int i = 0; i < 2; i++) {
        const int mr = m0 + wm * 32 + i * 16 + (lane >> 2);
        #pragma unroll
        for (int half = 0; half < 2; half++) {
            const int m = mr + half * 8;
            if (m >= M) continue;
            float* outp = C + (size_t)m * 512 + cbase;
            #pragma unroll
            for (int j = 0; j < 8; j++) {
                float o0 = acc[i][j][half * 2 + 0];
                float o1 = acc[i][j][half * 2 + 1];
                if (bias) {
                    o0 += bias[cbase + j * 8];
                    o1 += bias[cbase + j * 8 + 1];
                }
                if (RELU) { o0 = fmaxf(o0, 0.f); o1 = fmaxf(o1, 0.f); }
                *(float2*)(outp + j * 8) = make_float2(o0, o1);
            }
        }
    }
}

// ---------------- pair-sum reduction (sliced) ----------------
__global__ void reduce_part()
{
    const int idx = blockIdx.x * 256 + threadIdx.x;   // (b,h)
    const int s   = blockIdx.y;
    const int b = idx >> 9, h = idx & 511;
    const float* base = g_H3 + (size_t)b * NP * 512 + h;
    float acc = 0.f;
    const int p0 = s * 125;
    #pragma unroll 5
    for (int p = p0; p < p0 + 125; p++) acc += base[(size_t)p * 512];
    g_PART[s * (B_ * H_) + idx] = acc;
}
__global__ void reduce_final()
{
    const int idx = blockIdx.x * 256 + threadIdx.x;
    const int b = idx >> 9, h = idx & 511;
    float s = 0.f;
    #pragma unroll
    for (int k = 0; k < SLICES; k++) s += g_PART[k * (B_ * H_) + idx];
    const float* base = g_H3 + (size_t)b * NP * 512 + h;
    #pragma unroll
    for (int i = 0; i < N_; i++) s -= base[(size_t)(i * 26) * 512];
    g_AGG[idx] = s;
}

// ---------------- small fp32 FC head ----------------
template<bool RELU>
__global__ void fc_kernel(const float* __restrict__ X, const float* __restrict__ W,
                          const float* __restrict__ bias, float* __restrict__ Y,
                          int Nout)
{
    __shared__ float xs[512];
    const int b = blockIdx.x;
    for (int k = threadIdx.x; k < 512; k += blockDim.x) xs[k] = X[b * 512 + k];
    __syncthreads();
    for (int n = threadIdx.x; n < Nout; n += blockDim.x) {
        float s = bias[n];
        #pragma unroll 8
        for (int k = 0; k < 512; k++) s = fmaf(xs[k], W[k * Nout + n], s);
        if (RELU) s = fmaxf(s, 0.f);
        Y[b * Nout + n] = s;
    }
}

// ======================================================================
extern "C" void kernel_launch(void* const* d_in, const int* in_sizes, int n_in,
                              void* d_out, int out_size)
{
    const float* x    = (const float*)d_in[0];
    const float* g_w1 = (const float*)d_in[1];
    const float* g_b1 = (const float*)d_in[2];
    const float* g_w2 = (const float*)d_in[3];
    const float* g_b2 = (const float*)d_in[4];
    const float* g_w3 = (const float*)d_in[5];
    const float* g_b3 = (const float*)d_in[6];
    const float* f_w1 = (const float*)d_in[7];
    const float* f_b1 = (const float*)d_in[8];
    const float* f_w2 = (const float*)d_in[9];
    const float* f_b2 = (const float*)d_in[10];
    const float* f_w3 = (const float*)d_in[11];
    const float* f_b3 = (const float*)d_in[12];
    float* out = (float*)d_out;

    float *pU, *pV, *pH2, *pH3, *pAGG, *pZ1, *pZ2;
    cudaGetSymbolAddress((void**)&pU,   g_U);
    cudaGetSymbolAddress((void**)&pV,   g_V);
    cudaGetSymbolAddress((void**)&pH2,  g_H2);
    cudaGetSymbolAddress((void**)&pH3,  g_H3);
    cudaGetSymbolAddress((void**)&pAGG, g_AGG);
    cudaGetSymbolAddress((void**)&pZ1,  g_Z1);
    cudaGetSymbolAddress((void**)&pZ2,  g_Z2);

    cudaFuncSetAttribute(gemm_tc<0,0>, cudaFuncAttributeMaxDynamicSharedMemorySize, SMEM_BYTES);
    cudaFuncSetAttribute(gemm_tc<1,1>, cudaFuncAttributeMaxDynamicSharedMemorySize, SMEM_BYTES);
    cudaFuncSetAttribute(gemm_tc<0,1>, cudaFuncAttributeMaxDynamicSharedMemorySize, SMEM_BYTES);

    // U = x @ W1[0:512] + b1 ;  V = x @ W1[512:1024]   (layer-1 factorized)
    dim3 gsmall(4, (M_ROWS + 127) / 128);
    gemm_tc<0,0><<<gsmall, 256, SMEM_BYTES>>>(x, g_w1,             g_b1,    pU, M_ROWS);
    gemm_tc<0,0><<<gsmall, 256, SMEM_BYTES>>>(x, g_w1 + 512 * 512, nullptr, pV, M_ROWS);

    // h2 = relu( relu(U_i + V_j) @ W2 + b2 )  — h1 generated in the A-loader
    dim3 gbig(4, (M_PAIRS + 127) / 128);
    gemm_tc<1,1><<<gbig, 256, SMEM_BYTES>>>(nullptr, g_w2, g_b2, pH2, M_PAIRS);

    // h3 = relu( h2 @ W3 + b3 )
    gemm_tc<0,1><<<gbig, 256, SMEM_BYTES>>>(pH2, g_w3, g_b3, pH3, M_PAIRS);

    // agg over pairs i != j
    reduce_part <<<dim3(64, SLICES), 256>>>();
    reduce_final<<<64, 256>>>();

    // f head (fp32)
    fc_kernel<true ><<<B_, 512>>>(pAGG, f_w1, f_b1, pZ1, 512);
    fc_kernel<true ><<<B_, 512>>>(pZ1,  f_w2, f_b2, pZ2, 512);
    fc_kernel<false><<<B_, 512>>>(pZ2,  f_w3, f_b3, out, 1000);
}

// round 4
// speedup vs baseline: 3.3618x; 1.5564x over previous
#include <cuda_runtime.h>

typedef unsigned int u32;

namespace {
constexpr int B_ = 32, N_ = 25, H_ = 512, C_ = 1000;
constexpr int NP      = N_ * N_;   // 625
constexpr int M_PAIRS = B_ * NP;   // 20000
constexpr int M_ROWS  = B_ * N_;   // 800

constexpr int ABUF      = 32 * 132;
constexpr int BBUF      = 64 * 66;
constexpr int BUFSTRIDE = ABUF + BBUF;
constexpr int SMEM_BYTES = 2 * BUFSTRIDE * 4;   // 67584 B
}

// ---------------- scratch (allocation-free device globals) ----------------
__device__ float g_U [M_ROWS * H_];
__device__ float g_V [M_ROWS * H_];
__device__ float g_H2[(size_t)M_PAIRS * H_];
__device__ float g_PART[160 * H_];              // per-(b,slice) column partials

// ---------------- helpers ----------------
__device__ __forceinline__ u32 tf32u(float x) {
    u32 r; asm("cvt.rna.tf32.f32 %0, %1;" : "=r"(r) : "f"(x));
    return r;
}
__device__ __forceinline__ void mma8(float* d, const u32* a, const u32* b) {
    asm volatile(
        "mma.sync.aligned.m16n8k8.row.col.f32.tf32.tf32.f32 "
        "{%0,%1,%2,%3}, {%4,%5,%6,%7}, {%8,%9}, {%0,%1,%2,%3};\n"
        : "+f"(d[0]), "+f"(d[1]), "+f"(d[2]), "+f"(d[3])
        : "r"(a[0]), "r"(a[1]), "r"(a[2]), "r"(a[3]), "r"(b[0]), "r"(b[1]));
}

// ======================================================================
// tf32 tensor-core GEMM: C[M,512] = A[M,512] @ W  (W row-major [512,512])
// tile 128m x 128n x 32k, double-buffered, fragments pre-scattered in smem.
// AMODE 0: plain A rows (by*128 grid)
// AMODE 1: A row m = relu(U[b,i] + V[b,j]) on the fly (by*128 grid)
// AMODE 2: UV split — grid.x=8; half=n0>>9 picks W1 half and U/V output
// REDUCE 1: b-aligned grid (5 tiles of 125 rows per b); no C store; write
//           masked (i!=j) column sums to C (=g_PART[by][512]).
// ======================================================================
template<int AMODE, int REDUCE, int RELU>
__global__ __launch_bounds__(256, 2)
void gemm_tc(const float* __restrict__ A, const float* __restrict__ Bw,
             const float* __restrict__ bias, float* __restrict__ C,
             float* __restrict__ C2, int M)
{
    extern __shared__ u32 smem[];

    const int tid  = threadIdx.x;
    const int lane = tid & 31;
    const int wid  = tid >> 5;
    const int wm   = wid >> 1;
    const int wn   = wid & 1;
    const int by   = blockIdx.y;
    const int n0   = blockIdx.x * 128;

    // UV-split runtime selection
    const float* Bsrc = Bw;
    float*       Cdst = C;
    const float* beff = bias;
    int n0e = n0;
    if (AMODE == 2) {
        const int half = n0 >> 9;
        n0e = n0 & 511;
        if (half) { Bsrc = Bw + 512 * 512; Cdst = C2; beff = nullptr; }
    }

    // row base for this CTA
    int row_base;
    if (REDUCE) row_base = (by / 5) * NP + (by % 5) * 125;
    else        row_base = by * 128;
    const int row_cap = REDUCE ? 125 : (M - row_base);

    // ---- producer mappings ----
    const int lr8 = tid >> 3;
    const int kq  = tid & 7;
    const int kb8 = tid >> 5;
    const int n4  = (tid & 31) * 4;

    const float* pu[4];
    const float* pv[4];
    #pragma unroll
    for (int q = 0; q < 4; q++) {
        const int ml = lr8 + 32 * q;
        int m = row_base + ((ml < row_cap) ? ml : 0);
        if (AMODE == 1) {
            int b = m / NP; int r = m - b * NP;
            int i = r / N_; int j = r - i * N_;
            pu[q] = g_U + (size_t)(b * N_ + i) * 512;
            pv[q] = g_V + (size_t)(b * N_ + j) * 512;
        } else {
            pu[q] = A + (size_t)m * 512;
        }
    }

    float4 sau[4], sav[4], sb[4];

    auto ldg_stage = [&](int kt) {
        const int kb = kt * 32 + kq * 4;
        #pragma unroll
        for (int q = 0; q < 4; q++) {
            sau[q] = *(const float4*)(pu[q] + kb);
            if (AMODE == 1) sav[q] = *(const float4*)(pv[q] + kb);
        }
        const int kbB = kt * 32 + kb8;
        #pragma unroll
        for (int q = 0; q < 4; q++)
            sb[q] = *(const float4*)(Bsrc + (size_t)(kbB + 8 * q) * 512 + n0e + n4);
    };

    auto sts_a = [&](int buf) {
        u32* base = smem + buf * BUFSTRIDE;
        const int ktile = kq >> 1;
        const int slot0 = 2 * (kq & 1);
        #pragma unroll
        for (int q = 0; q < 4; q++) {
            const int ml = lr8 + 32 * q;
            const int mt = ml >> 4;
            const int r  = ml & 7;
            const int hm = (ml >> 3) & 1;
            u32* dst = base + (mt * 4 + ktile) * 132 + r * 16 + slot0 + hm;
            float v0, v1, v2, v3;
            if (AMODE == 1) {
                v0 = fmaxf(sau[q].x + sav[q].x, 0.f);
                v1 = fmaxf(sau[q].y + sav[q].y, 0.f);
                v2 = fmaxf(sau[q].z + sav[q].z, 0.f);
                v3 = fmaxf(sau[q].w + sav[q].w, 0.f);
            } else {
                v0 = sau[q].x; v1 = sau[q].y; v2 = sau[q].z; v3 = sau[q].w;
            }
            dst[0]  = tf32u(v0);
            dst[4]  = tf32u(v1);
            dst[8]  = tf32u(v2);
            dst[12] = tf32u(v3);
        }
    };

    auto sts_b = [&](int buf) {
        u32* base = smem + buf * BUFSTRIDE + ABUF;
        const int c    = kb8 & 3;
        const int slot = kb8 >> 2;
        #pragma unroll
        for (int q = 0; q < 4; q++) {
            float vv[4] = { sb[q].x, sb[q].y, sb[q].z, sb[q].w };
            #pragma unroll
            for (int j = 0; j < 4; j++) {
                const int nn = n4 + j;
                base[(q * 16 + (nn >> 3)) * 66 + ((nn & 7) * 4 + c) * 2 + slot]
                    = tf32u(vv[j]);
            }
        }
    };

    float acc[2][8][4] = {};

    ldg_stage(0);
    sts_a(0);
    sts_b(0);
    __syncthreads();

    for (int kt = 0; kt < 16; kt++) {
        const int buf   = kt & 1;
        const bool more = (kt < 15);
        if (more) ldg_stage(kt + 1);
        if (more) sts_a(buf ^ 1);

        const u32* ab = smem + buf * BUFSTRIDE;
        const u32* bb = ab + ABUF;
        #pragma unroll
        for (int ks = 0; ks < 4; ks++) {
            uint4 af0 = *(const uint4*)(ab + ((wm * 2 + 0) * 4 + ks) * 132 + lane * 4);
            uint4 af1 = *(const uint4*)(ab + ((wm * 2 + 1) * 4 + ks) * 132 + lane * 4);
            #pragma unroll
            for (int j = 0; j < 8; j++) {
                uint2 bf = *(const uint2*)(bb + (ks * 16 + wn * 8 + j) * 66 + lane * 2);
                mma8(acc[0][j], (const u32*)&af0, (const u32*)&bf);
                mma8(acc[1][j], (const u32*)&af1, (const u32*)&bf);
            }
        }
        if (more) sts_b(buf ^ 1);
        __syncthreads();
    }

    const int cbase = n0e + wn * 64 + (lane & 3) * 2;

    if (REDUCE) {
        // ---- fused masked column reduction (bias+relu first) ----
        const int s = by % 5;
        float csum[8][2];
        #pragma unroll
        for (int j = 0; j < 8; j++) { csum[j][0] = 0.f; csum[j][1] = 0.f; }
        #pragma unroll
        for (int i = 0; i < 2; i++) {
            #pragma unroll
            for (int half = 0; half < 2; half++) {
                const int ml = wm * 32 + i * 16 + half * 8 + (lane >> 2);
                const int p  = s * 125 + ml;
                const int ii = p / 25, jj = p - ii * 25;
                if ((ml < 125) && (ii != jj)) {
                    #pragma unroll
                    for (int j = 0; j < 8; j++) {
                        float o0 = acc[i][j][half * 2 + 0] + beff[cbase + j * 8];
                        float o1 = acc[i][j][half * 2 + 1] + beff[cbase + j * 8 + 1];
                        csum[j][0] += fmaxf(o0, 0.f);
                        csum[j][1] += fmaxf(o1, 0.f);
                    }
                }
            }
        }
        #pragma unroll
        for (int j = 0; j < 8; j++)
            #pragma unroll
            for (int c = 0; c < 2; c++) {
                float v = csum[j][c];
                v += __shfl_xor_sync(0xffffffffu, v, 4);
                v += __shfl_xor_sync(0xffffffffu, v, 8);
                v += __shfl_xor_sync(0xffffffffu, v, 16);
                csum[j][c] = v;
            }
        float* red = (float*)smem;
        if ((lane >> 2) == 0) {
            #pragma unroll
            for (int j = 0; j < 8; j++) {
                red[wm * 128 + wn * 64 + j * 8 + (lane & 3) * 2 + 0] = csum[j][0];
                red[wm * 128 + wn * 64 + j * 8 + (lane & 3) * 2 + 1] = csum[j][1];
            }
        }
        __syncthreads();
        if (tid < 128) {
            float v = red[tid] + red[128 + tid] + red[256 + tid] + red[384 + tid];
            Cdst[(size_t)by * 512 + n0 + tid] = v;
        }
        return;
    }

    // ---- standard epilogue: bias + relu, fp32 stores ----
    #pragma unroll
    for (int i = 0; i < 2; i++) {
        const int mr = wm * 32 + i * 16 + (lane >> 2);
        #pragma unroll
        for (int half = 0; half < 2; half++) {
            const int ml = mr + half * 8;
            if (ml >= row_cap) continue;
            float* outp = Cdst + (size_t)(row_base + ml) * 512 + cbase;
            #pragma unroll
            for (int j = 0; j < 8; j++) {
                float o0 = acc[i][j][half * 2 + 0];
                float o1 = acc[i][j][half * 2 + 1];
                if (beff) {
                    o0 += beff[cbase + j * 8];
                    o1 += beff[cbase + j * 8 + 1];
                }
                if (RELU) { o0 = fmaxf(o0, 0.f); o1 = fmaxf(o1, 0.f); }
                *(float2*)(outp + j * 8) = make_float2(o0, o1);
            }
        }
    }
}

// ---------------- fused f-head: partial-sum finish + 3 FC layers ----------------
__global__ __launch_bounds__(512)
void head_kernel(const float* __restrict__ f_w1, const float* __restrict__ f_b1,
                 const float* __restrict__ f_w2, const float* __restrict__ f_b2,
                 const float* __restrict__ f_w3, const float* __restrict__ f_b3,
                 float* __restrict__ out)
{
    __shared__ float s0[512];
    __shared__ float s1[512];
    const int b = blockIdx.x;
    const int n = threadIdx.x;

    // agg = sum of 5 slice partials
    {
        const float* p = g_PART + (size_t)(b * 5) * 512 + n;
        s0[n] = p[0] + p[512] + p[1024] + p[1536] + p[2048];
    }
    __syncthreads();
    // z1
    {
        float a = f_b1[n];
        #pragma unroll 8
        for (int k = 0; k < 512; k++) a = fmaf(s0[k], f_w1[k * 512 + n], a);
        s1[n] = fmaxf(a, 0.f);
    }
    __syncthreads();
    // z2
    {
        float a = f_b2[n];
        #pragma unroll 8
        for (int k = 0; k < 512; k++) a = fmaf(s1[k], f_w2[k * 512 + n], a);
        s0[n] = fmaxf(a, 0.f);
    }
    __syncthreads();
    // logits
    for (int c = n; c < C_; c += 512) {
        float a = f_b3[c];
        #pragma unroll 8
        for (int k = 0; k < 512; k++) a = fmaf(s0[k], f_w3[k * C_ + c], a);
        out[(size_t)b * C_ + c] = a;
    }
}

// ======================================================================
extern "C" void kernel_launch(void* const* d_in, const int* in_sizes, int n_in,
                              void* d_out, int out_size)
{
    const float* x    = (const float*)d_in[0];
    const float* g_w1 = (const float*)d_in[1];
    const float* g_b1 = (const float*)d_in[2];
    const float* g_w2 = (const float*)d_in[3];
    const float* g_b2 = (const float*)d_in[4];
    const float* g_w3 = (const float*)d_in[5];
    const float* g_b3 = (const float*)d_in[6];
    const float* f_w1 = (const float*)d_in[7];
    const float* f_b1 = (const float*)d_in[8];
    const float* f_w2 = (const float*)d_in[9];
    const float* f_b2 = (const float*)d_in[10];
    const float* f_w3 = (const float*)d_in[11];
    const float* f_b3 = (const float*)d_in[12];
    float* out = (float*)d_out;

    float *pU, *pV, *pH2, *pPART;
    cudaGetSymbolAddress((void**)&pU,    g_U);
    cudaGetSymbolAddress((void**)&pV,    g_V);
    cudaGetSymbolAddress((void**)&pH2,   g_H2);
    cudaGetSymbolAddress((void**)&pPART, g_PART);

    cudaFuncSetAttribute(gemm_tc<2,0,0>, cudaFuncAttributeMaxDynamicSharedMemorySize, SMEM_BYTES);
    cudaFuncSetAttribute(gemm_tc<1,0,1>, cudaFuncAttributeMaxDynamicSharedMemorySize, SMEM_BYTES);
    cudaFuncSetAttribute(gemm_tc<0,1,1>, cudaFuncAttributeMaxDynamicSharedMemorySize, SMEM_BYTES);

    // U | V in one launch (layer-1 factorized; half = n0>>9)
    gemm_tc<2,0,0><<<dim3(8, 7), 256, SMEM_BYTES>>>(x, g_w1, g_b1, pU, pV, M_ROWS);

    // h2 = relu( relu(U_i + V_j) @ W2 + b2 )
    gemm_tc<1,0,1><<<dim3(4, 157), 256, SMEM_BYTES>>>(nullptr, g_w2, g_b2, pH2, nullptr, M_PAIRS);

    // h3 GEMM fused with masked (i!=j) pair reduction -> g_PART[160][512]
    gemm_tc<0,1,1><<<dim3(4, 160), 256, SMEM_BYTES>>>(pH2, g_w3, g_b3, pPART, nullptr, M_PAIRS);

    // fused f-head
    head_kernel<<<B_, 512>>>(f_w1, f_b1, f_w2, f_b2, f_w3, f_b3, out);
}

// round 5
// speedup vs baseline: 3.8817x; 1.1546x over previous
#include <cuda_runtime.h>

typedef unsigned int u32;

namespace {
constexpr int B_ = 32, N_ = 25, H_ = 512, C_ = 1000;
constexpr int NP      = N_ * N_;   // 625
constexpr int M_PAIRS = B_ * NP;   // 20000
constexpr int M_ROWS  = B_ * N_;   // 800

constexpr int ABUF      = 32 * 132;
constexpr int BBUF      = 64 * 66;
constexpr int BUFSTRIDE = ABUF + BBUF;
constexpr int SMEM_BYTES = 2 * BUFSTRIDE * 4;   // 67584 B
}

// ---------------- scratch (allocation-free device globals) ----------------
__device__ float g_U [M_ROWS * H_];
__device__ float g_V [M_ROWS * H_];
__device__ float g_H2[(size_t)M_PAIRS * H_];
__device__ float g_PART[160 * H_];              // per-(b,slice) column partials
__device__ float g_Z1 [B_ * H_];
__device__ float g_Z2 [B_ * H_];

// ---------------- helpers ----------------
__device__ __forceinline__ u32 tf32u(float x) {
    u32 r; asm("cvt.rna.tf32.f32 %0, %1;" : "=r"(r) : "f"(x));
    return r;
}
__device__ __forceinline__ void mma8(float* d, const u32* a, const u32* b) {
    asm volatile(
        "mma.sync.aligned.m16n8k8.row.col.f32.tf32.tf32.f32 "
        "{%0,%1,%2,%3}, {%4,%5,%6,%7}, {%8,%9}, {%0,%1,%2,%3};\n"
        : "+f"(d[0]), "+f"(d[1]), "+f"(d[2]), "+f"(d[3])
        : "r"(a[0]), "r"(a[1]), "r"(a[2]), "r"(a[3]), "r"(b[0]), "r"(b[1]));
}

// ======================================================================
// tf32 tensor-core GEMM: C[M,512] = A[M,512] @ W  (W row-major [512,512])
// tile 128m x 128n x 32k, double-buffered, fragments pre-scattered in smem.
// AMODE 0: plain A rows; AMODE 1: relu(U_i+V_j) on the fly;
// AMODE 2: UV split (grid.x=8, half = n0>>9)
// REDUCE 1: b-aligned tiles (5 x 125 rows / b); masked (i!=j) column sums.
// ======================================================================
template<int AMODE, int REDUCE, int RELU>
__global__ __launch_bounds__(256, 2)
void gemm_tc(const float* __restrict__ A, const float* __restrict__ Bw,
             const float* __restrict__ bias, float* __restrict__ C,
             float* __restrict__ C2, int M)
{
    extern __shared__ u32 smem[];

    const int tid  = threadIdx.x;
    const int lane = tid & 31;
    const int wid  = tid >> 5;
    const int wm   = wid >> 1;
    const int wn   = wid & 1;
    const int by   = blockIdx.y;
    const int n0   = blockIdx.x * 128;

    const float* Bsrc = Bw;
    float*       Cdst = C;
    const float* beff = bias;
    int n0e = n0;
    if (AMODE == 2) {
        const int half = n0 >> 9;
        n0e = n0 & 511;
        if (half) { Bsrc = Bw + 512 * 512; Cdst = C2; beff = nullptr; }
    }

    int row_base;
    if (REDUCE) row_base = (by / 5) * NP + (by % 5) * 125;
    else        row_base = by * 128;
    const int row_cap = REDUCE ? 125 : (M - row_base);

    const int lr8 = tid >> 3;
    const int kq  = tid & 7;
    const int kb8 = tid >> 5;
    const int n4  = (tid & 31) * 4;

    const float* pu[4];
    const float* pv[4];
    #pragma unroll
    for (int q = 0; q < 4; q++) {
        const int ml = lr8 + 32 * q;
        int m = row_base + ((ml < row_cap) ? ml : 0);
        if (AMODE == 1) {
            int b = m / NP; int r = m - b * NP;
            int i = r / N_; int j = r - i * N_;
            pu[q] = g_U + (size_t)(b * N_ + i) * 512;
            pv[q] = g_V + (size_t)(b * N_ + j) * 512;
        } else {
            pu[q] = A + (size_t)m * 512;
        }
    }

    float4 sau[4], sav[4], sb[4];

    auto ldg_stage = [&](int kt) {
        const int kb = kt * 32 + kq * 4;
        #pragma unroll
        for (int q = 0; q < 4; q++) {
            sau[q] = *(const float4*)(pu[q] + kb);
            if (AMODE == 1) sav[q] = *(const float4*)(pv[q] + kb);
        }
        const int kbB = kt * 32 + kb8;
        #pragma unroll
        for (int q = 0; q < 4; q++)
            sb[q] = *(const float4*)(Bsrc + (size_t)(kbB + 8 * q) * 512 + n0e + n4);
    };

    auto sts_a = [&](int buf) {
        u32* base = smem + buf * BUFSTRIDE;
        const int ktile = kq >> 1;
        const int slot0 = 2 * (kq & 1);
        #pragma unroll
        for (int q = 0; q < 4; q++) {
            const int ml = lr8 + 32 * q;
            const int mt = ml >> 4;
            const int r  = ml & 7;
            const int hm = (ml >> 3) & 1;
            u32* dst = base + (mt * 4 + ktile) * 132 + r * 16 + slot0 + hm;
            float v0, v1, v2, v3;
            if (AMODE == 1) {
                v0 = fmaxf(sau[q].x + sav[q].x, 0.f);
                v1 = fmaxf(sau[q].y + sav[q].y, 0.f);
                v2 = fmaxf(sau[q].z + sav[q].z, 0.f);
                v3 = fmaxf(sau[q].w + sav[q].w, 0.f);
            } else {
                v0 = sau[q].x; v1 = sau[q].y; v2 = sau[q].z; v3 = sau[q].w;
            }
            dst[0]  = tf32u(v0);
            dst[4]  = tf32u(v1);
            dst[8]  = tf32u(v2);
            dst[12] = tf32u(v3);
        }
    };

    auto sts_b = [&](int buf) {
        u32* base = smem + buf * BUFSTRIDE + ABUF;
        const int c    = kb8 & 3;
        const int slot = kb8 >> 2;
        #pragma unroll
        for (int q = 0; q < 4; q++) {
            float vv[4] = { sb[q].x, sb[q].y, sb[q].z, sb[q].w };
            #pragma unroll
            for (int j = 0; j < 4; j++) {
                const int nn = n4 + j;
                base[(q * 16 + (nn >> 3)) * 66 + ((nn & 7) * 4 + c) * 2 + slot]
                    = tf32u(vv[j]);
            }
        }
    };

    float acc[2][8][4] = {};

    ldg_stage(0);
    sts_a(0);
    sts_b(0);
    __syncthreads();

    for (int kt = 0; kt < 16; kt++) {
        const int buf   = kt & 1;
        const bool more = (kt < 15);
        if (more) ldg_stage(kt + 1);
        if (more) sts_a(buf ^ 1);

        const u32* ab = smem + buf * BUFSTRIDE;
        const u32* bb = ab + ABUF;
        #pragma unroll
        for (int ks = 0; ks < 4; ks++) {
            uint4 af0 = *(const uint4*)(ab + ((wm * 2 + 0) * 4 + ks) * 132 + lane * 4);
            uint4 af1 = *(const uint4*)(ab + ((wm * 2 + 1) * 4 + ks) * 132 + lane * 4);
            #pragma unroll
            for (int j = 0; j < 8; j++) {
                uint2 bf = *(const uint2*)(bb + (ks * 16 + wn * 8 + j) * 66 + lane * 2);
                mma8(acc[0][j], (const u32*)&af0, (const u32*)&bf);
                mma8(acc[1][j], (const u32*)&af1, (const u32*)&bf);
            }
        }
        if (more) sts_b(buf ^ 1);
        __syncthreads();
    }

    const int cbase = n0e + wn * 64 + (lane & 3) * 2;

    if (REDUCE) {
        const int s = by % 5;
        float csum[8][2];
        #pragma unroll
        for (int j = 0; j < 8; j++) { csum[j][0] = 0.f; csum[j][1] = 0.f; }
        #pragma unroll
        for (int i = 0; i < 2; i++) {
            #pragma unroll
            for (int half = 0; half < 2; half++) {
                const int ml = wm * 32 + i * 16 + half * 8 + (lane >> 2);
                const int p  = s * 125 + ml;
                const int ii = p / 25, jj = p - ii * 25;
                if ((ml < 125) && (ii != jj)) {
                    #pragma unroll
                    for (int j = 0; j < 8; j++) {
                        float o0 = acc[i][j][half * 2 + 0] + beff[cbase + j * 8];
                        float o1 = acc[i][j][half * 2 + 1] + beff[cbase + j * 8 + 1];
                        csum[j][0] += fmaxf(o0, 0.f);
                        csum[j][1] += fmaxf(o1, 0.f);
                    }
                }
            }
        }
        #pragma unroll
        for (int j = 0; j < 8; j++)
            #pragma unroll
            for (int c = 0; c < 2; c++) {
                float v = csum[j][c];
                v += __shfl_xor_sync(0xffffffffu, v, 4);
                v += __shfl_xor_sync(0xffffffffu, v, 8);
                v += __shfl_xor_sync(0xffffffffu, v, 16);
                csum[j][c] = v;
            }
        float* red = (float*)smem;
        if ((lane >> 2) == 0) {
            #pragma unroll
            for (int j = 0; j < 8; j++) {
                red[wm * 128 + wn * 64 + j * 8 + (lane & 3) * 2 + 0] = csum[j][0];
                red[wm * 128 + wn * 64 + j * 8 + (lane & 3) * 2 + 1] = csum[j][1];
            }
        }
        __syncthreads();
        if (tid < 128) {
            float v = red[tid] + red[128 + tid] + red[256 + tid] + red[384 + tid];
            Cdst[(size_t)by * 512 + n0 + tid] = v;
        }
        return;
    }

    #pragma unroll
    for (int i = 0; i < 2; i++) {
        const int mr = wm * 32 + i * 16 + (lane >> 2);
        #pragma unroll
        for (int half = 0; half < 2; half++) {
            const int ml = mr + half * 8;
            if (ml >= row_cap) continue;
            float* outp = Cdst + (size_t)(row_base + ml) * 512 + cbase;
            #pragma unroll
            for (int j = 0; j < 8; j++) {
                float o0 = acc[i][j][half * 2 + 0];
                float o1 = acc[i][j][half * 2 + 1];
                if (beff) {
                    o0 += beff[cbase + j * 8];
                    o1 += beff[cbase + j * 8 + 1];
                }
                if (RELU) { o0 = fmaxf(o0, 0.f); o1 = fmaxf(o1, 0.f); }
                *(float2*)(outp + j * 8) = make_float2(o0, o1);
            }
        }
    }
}

// ======================================================================
// Head FC layer, wide-parallel: grid (n-tiles of 64, 32 b), block 256 =
// 4 k-groups x 64 n-lanes (coalesced W rows), smem cross-group reduce.
// AGG: X row b = sum of 5 slice partials in g_PART.
// ======================================================================
template<int AGG, int RELU>
__global__ __launch_bounds__(256)
void head_fc(const float* __restrict__ X, const float* __restrict__ W,
             const float* __restrict__ bias, float* __restrict__ Y, int Nout)
{
    __shared__ float xs[512];
    __shared__ float red[4][64];

    const int b   = blockIdx.y;
    const int n0  = blockIdx.x * 64;
    const int tid = threadIdx.x;
    const int nl  = tid & 63;
    const int kg  = tid >> 6;          // 0..3, k-range [kg*128, kg*128+128)

    // stage X row (or aggregate of 5 partials)
    #pragma unroll
    for (int t = 0; t < 2; t++) {
        const int k = tid + t * 256;
        if (AGG) {
            const float* p = g_PART + (size_t)(b * 5) * 512 + k;
            xs[k] = p[0] + p[512] + p[1024] + p[1536] + p[2048];
        } else {
            xs[k] = X[(size_t)b * 512 + k];
        }
    }
    __syncthreads();

    const int n = n0 + nl;
    float acc = 0.f;
    if (n < Nout) {
        const float* wp = W + (size_t)(kg * 128) * Nout + n;
        #pragma unroll 8
        for (int kk = 0; kk < 128; kk++)
            acc = fmaf(xs[kg * 128 + kk], wp[(size_t)kk * Nout], acc);
    }
    red[kg][nl] = acc;
    __syncthreads();
    if (kg == 0 && n < Nout) {
        float v = red[0][nl] + red[1][nl] + red[2][nl] + red[3][nl] + bias[n];
        if (RELU) v = fmaxf(v, 0.f);
        Y[(size_t)b * Nout + n] = v;
    }
}

// ======================================================================
extern "C" void kernel_launch(void* const* d_in, const int* in_sizes, int n_in,
                              void* d_out, int out_size)
{
    const float* x    = (const float*)d_in[0];
    const float* g_w1 = (const float*)d_in[1];
    const float* g_b1 = (const float*)d_in[2];
    const float* g_w2 = (const float*)d_in[3];
    const float* g_b2 = (const float*)d_in[4];
    const float* g_w3 = (const float*)d_in[5];
    const float* g_b3 = (const float*)d_in[6];
    const float* f_w1 = (const float*)d_in[7];
    const float* f_b1 = (const float*)d_in[8];
    const float* f_w2 = (const float*)d_in[9];
    const float* f_b2 = (const float*)d_in[10];
    const float* f_w3 = (const float*)d_in[11];
    const float* f_b3 = (const float*)d_in[12];
    float* out = (float*)d_out;

    float *pU, *pV, *pH2, *pPART, *pZ1, *pZ2;
    cudaGetSymbolAddress((void**)&pU,    g_U);
    cudaGetSymbolAddress((void**)&pV,    g_V);
    cudaGetSymbolAddress((void**)&pH2,   g_H2);
    cudaGetSymbolAddress((void**)&pPART, g_PART);
    cudaGetSymbolAddress((void**)&pZ1,   g_Z1);
    cudaGetSymbolAddress((void**)&pZ2,   g_Z2);

    cudaFuncSetAttribute(gemm_tc<2,0,0>, cudaFuncAttributeMaxDynamicSharedMemorySize, SMEM_BYTES);
    cudaFuncSetAttribute(gemm_tc<1,0,1>, cudaFuncAttributeMaxDynamicSharedMemorySize, SMEM_BYTES);
    cudaFuncSetAttribute(gemm_tc<0,1,1>, cudaFuncAttributeMaxDynamicSharedMemorySize, SMEM_BYTES);

    // U | V in one launch (layer-1 factorized; half = n0>>9)
    gemm_tc<2,0,0><<<dim3(8, 7), 256, SMEM_BYTES>>>(x, g_w1, g_b1, pU, pV, M_ROWS);

    // h2 = relu( relu(U_i + V_j) @ W2 + b2 )
    gemm_tc<1,0,1><<<dim3(4, 157), 256, SMEM_BYTES>>>(nullptr, g_w2, g_b2, pH2, nullptr, M_PAIRS);

    // h3 GEMM fused with masked (i!=j) pair reduction -> g_PART[160][512]
    gemm_tc<0,1,1><<<dim3(4, 160), 256, SMEM_BYTES>>>(pH2, g_w3, g_b3, pPART, nullptr, M_PAIRS);

    // f head: 3 wide-parallel layers (agg folded into layer 1's loader)
    head_fc<1,1><<<dim3(8,  B_), 256>>>(nullptr, f_w1, f_b1, pZ1, 512);
    head_fc<0,1><<<dim3(8,  B_), 256>>>(pZ1,     f_w2, f_b2, pZ2, 512);
    head_fc<0,0><<<dim3(16, B_), 256>>>(pZ2,     f_w3, f_b3, out, C_);
}